// round 4
// baseline (speedup 1.0000x reference)
#include <cuda_runtime.h>

#define N_NODES 100000
#define N_EDGES 1600000
#define D 128
#define F4 32          // float4 per row
#define D_OUT 64
#define BN_EPS 1e-5f

typedef unsigned long long u64;

// ---------------- static device scratch (no allocations allowed) ----------------
__device__ int g_cnt[N_NODES];
__device__ int g_rowptr[N_NODES + 1];
__device__ int g_fill[N_NODES];
__device__ int g_col[N_EDGES];
__device__ float4 g_bufA[N_NODES * F4];  // t0, later t2
__device__ float4 g_bufB[N_NODES * F4];  // t1
__device__ __align__(16) float g_sum[3][D];   // colsum of pre-readout a (per layer)
__device__ __align__(16) float g_sq[3][D];    // colsum of a^2
__device__ __align__(16) float g_ro[3][D];    // readout: colsum of input fed into layer L

// ---------------- init ----------------
__global__ void zero_kernel() {
    int i = blockIdx.x * 256 + threadIdx.x;
    if (i < N_NODES) g_cnt[i] = 0;
    if (i < 3 * D) {
        (&g_sum[0][0])[i] = 0.f;
        (&g_sq[0][0])[i]  = 0.f;
        (&g_ro[0][0])[i]  = 0.f;
    }
}

// ---------------- CSR build (edge_index delivered as int32 by the harness) ----------------
__global__ void hist_kernel(const int* __restrict__ ei) {
    int t = blockIdx.x * 256 + threadIdx.x;
    if (t < N_EDGES / 4) {
        int4 d4 = ((const int4*)ei)[t];      // dst = edge_index[0]
        atomicAdd(&g_cnt[d4.x], 1);
        atomicAdd(&g_cnt[d4.y], 1);
        atomicAdd(&g_cnt[d4.z], 1);
        atomicAdd(&g_cnt[d4.w], 1);
    }
}

// single-block scan, 1024 threads x 8 items
__global__ void scan_kernel() {
    __shared__ int warp_sums[32];
    __shared__ int s_carry;
    int tid = threadIdx.x;
    int lane = tid & 31, wid = tid >> 5;
    if (tid == 0) s_carry = 0;
    __syncthreads();
    const int CHUNK = 1024 * 8;
    for (int base = 0; base < N_NODES; base += CHUNK) {
        int idx0 = base + tid * 8;
        int v[8], pre[8];
        int run = 0;
#pragma unroll
        for (int k = 0; k < 8; k++) {
            int i = idx0 + k;
            v[k] = (i < N_NODES) ? g_cnt[i] : 0;
            run += v[k];
            pre[k] = run;                    // inclusive within thread
        }
        int tsum = run;
        int x = tsum;
#pragma unroll
        for (int dsh = 1; dsh < 32; dsh <<= 1) {
            int y = __shfl_up_sync(0xffffffffu, x, dsh);
            if (lane >= dsh) x += y;
        }
        if (lane == 31) warp_sums[wid] = x;
        __syncthreads();
        if (wid == 0) {
            int w = warp_sums[lane];
#pragma unroll
            for (int dsh = 1; dsh < 32; dsh <<= 1) {
                int y = __shfl_up_sync(0xffffffffu, w, dsh);
                if (lane >= dsh) w += y;
            }
            warp_sums[lane] = w;
        }
        __syncthreads();
        int carry = s_carry;
        int off = carry + (wid > 0 ? warp_sums[wid - 1] : 0) + (x - tsum);
#pragma unroll
        for (int k = 0; k < 8; k++) {
            int i = idx0 + k;
            if (i < N_NODES) {
                int ex = off + (pre[k] - v[k]);  // exclusive prefix
                g_rowptr[i] = ex;
                g_fill[i] = ex;
            }
        }
        __syncthreads();
        if (tid == 0) s_carry = carry + warp_sums[31];
        __syncthreads();
    }
    if (threadIdx.x == 0) g_rowptr[N_NODES] = s_carry;  // == N_EDGES
}

__global__ void fill_kernel(const int* __restrict__ ei) {
    int t = blockIdx.x * 256 + threadIdx.x;
    if (t < N_EDGES / 4) {
        int4 d4 = ((const int4*)ei)[t];
        int4 s4 = ((const int4*)(ei + N_EDGES))[t];
        int p0 = atomicAdd(&g_fill[d4.x], 1);
        int p1 = atomicAdd(&g_fill[d4.y], 1);
        int p2 = atomicAdd(&g_fill[d4.z], 1);
        int p3 = atomicAdd(&g_fill[d4.w], 1);
        g_col[p0] = s4.x;
        g_col[p1] = s4.y;
        g_col[p2] = s4.z;
        g_col[p3] = s4.w;
    }
}

// normalize-on-the-fly of layer (L-1) outputs: relu(((t + ro) - mean) * scale + beta)
__device__ __forceinline__ float4 normf(float4 t, float4 ro, float4 mn, float4 sc, float4 bt) {
    float4 v;
    v.x = fmaxf(fmaf((t.x + ro.x) - mn.x, sc.x, bt.x), 0.f);
    v.y = fmaxf(fmaf((t.y + ro.y) - mn.y, sc.y, bt.y), 0.f);
    v.z = fmaxf(fmaf((t.z + ro.z) - mn.z, sc.z, bt.z), 0.f);
    v.w = fmaxf(fmaf((t.w + ro.w) - mn.w, sc.w, bt.w), 0.f);
    return v;
}

// ---------------- combine: normalize input rows on the fly, self + CSR-gathered agg;
// write pre-readout a; accumulate stats for this layer AND readout for this layer ----------------
template <bool NORM>
__global__ void __launch_bounds__(256) combine_kernel(int layer,
                                                      const float4* __restrict__ tin,
                                                      float4* __restrict__ tout,
                                                      const float* __restrict__ gamma,
                                                      const float* __restrict__ beta) {
    __shared__ float s_sc[D], s_mn[D], s_bt[D], s_ro[D];
    __shared__ float ssum[D], ssq[D], sro[D];
    int tid = threadIdx.x;
    if (tid < D) {
        ssum[tid] = 0.f; ssq[tid] = 0.f; sro[tid] = 0.f;
        if (NORM) {
            int pl = layer - 1;
            const float inv = 1.0f / (float)N_NODES;
            float mu = g_sum[pl][tid] * inv;
            float var = g_sq[pl][tid] * inv - mu * mu;   // shift-invariant variance
            float ro = g_ro[pl][tid];
            s_sc[tid] = gamma[pl * D + tid] * rsqrtf(var + BN_EPS);
            s_mn[tid] = ro + mu;                          // mean incl. readout
            s_bt[tid] = beta[pl * D + tid];
            s_ro[tid] = ro;
        }
    }
    __syncthreads();

    int lane = tid & 31;
    int gw = (blockIdx.x * 256 + tid) >> 5;
    int nw = (gridDim.x * 256) >> 5;
    float4 ro4, mn4, sc4, bt4;
    if (NORM) {
        ro4 = ((const float4*)s_ro)[lane];
        mn4 = ((const float4*)s_mn)[lane];
        sc4 = ((const float4*)s_sc)[lane];
        bt4 = ((const float4*)s_bt)[lane];
    }
    float4 ls = make_float4(0.f, 0.f, 0.f, 0.f);
    float4 lq = make_float4(0.f, 0.f, 0.f, 0.f);
    float4 lr = make_float4(0.f, 0.f, 0.f, 0.f);

    for (int i = gw; i < N_NODES; i += nw) {
        int beg = g_rowptr[i];
        int end = g_rowptr[i + 1];
        float4 a = tin[i * F4 + lane];
        if (NORM) a = normf(a, ro4, mn4, sc4, bt4);
        // self value == input fed into this layer -> accumulate readout for this layer
        lr.x += a.x; lr.y += a.y; lr.z += a.z; lr.w += a.w;
        int e = beg;
        for (; e + 1 < end; e += 2) {
            int j0 = g_col[e];
            int j1 = g_col[e + 1];
            float4 v0 = tin[j0 * F4 + lane];
            float4 v1 = tin[j1 * F4 + lane];
            if (NORM) { v0 = normf(v0, ro4, mn4, sc4, bt4); v1 = normf(v1, ro4, mn4, sc4, bt4); }
            a.x += v0.x; a.y += v0.y; a.z += v0.z; a.w += v0.w;
            a.x += v1.x; a.y += v1.y; a.z += v1.z; a.w += v1.w;
        }
        if (e < end) {
            int j = g_col[e];
            float4 v = tin[j * F4 + lane];
            if (NORM) v = normf(v, ro4, mn4, sc4, bt4);
            a.x += v.x; a.y += v.y; a.z += v.z; a.w += v.w;
        }
        // stats on pre-readout values (variance is shift-invariant)
        ls.x += a.x; ls.y += a.y; ls.z += a.z; ls.w += a.w;
        lq.x += a.x * a.x; lq.y += a.y * a.y; lq.z += a.z * a.z; lq.w += a.w * a.w;
        tout[i * F4 + lane] = a;               // NOTE: readout deferred to consumer
    }
    int f = lane * 4;
    atomicAdd(&ssum[f + 0], ls.x); atomicAdd(&ssum[f + 1], ls.y);
    atomicAdd(&ssum[f + 2], ls.z); atomicAdd(&ssum[f + 3], ls.w);
    atomicAdd(&ssq[f + 0], lq.x);  atomicAdd(&ssq[f + 1], lq.y);
    atomicAdd(&ssq[f + 2], lq.z);  atomicAdd(&ssq[f + 3], lq.w);
    atomicAdd(&sro[f + 0], lr.x);  atomicAdd(&sro[f + 1], lr.y);
    atomicAdd(&sro[f + 2], lr.z);  atomicAdd(&sro[f + 3], lr.w);
    __syncthreads();
    if (tid < D) {
        atomicAdd(&g_sum[layer][tid], ssum[tid]);
        atomicAdd(&g_sq[layer][tid], ssq[tid]);
        atomicAdd(&g_ro[layer][tid], sro[tid]);
    }
}

// ---------------- f32x2 packed fma helpers ----------------
__device__ __forceinline__ u64 pack2(float x) {
    u64 r; unsigned xi = __float_as_uint(x);
    asm("mov.b64 %0, {%1, %1};" : "=l"(r) : "r"(xi));
    return r;
}
__device__ __forceinline__ void ffma2(u64& d, u64 a, u64 b) {
    asm("fma.rn.f32x2 %0, %1, %2, %0;" : "+l"(d) : "l"(a), "l"(b));
}

// ---------------- final: fused (normalize+relu of layer2) @ W + b, packed f32x2 ----------------
// block: 256 threads, tile 128 rows x 64 cols; thread computes 8 rows x 4 cols (2 f32x2 pairs)
__global__ void __launch_bounds__(256) gemm_kernel(const float* __restrict__ W,
                                                   const float* __restrict__ b,
                                                   const float* __restrict__ gamma,
                                                   const float* __restrict__ beta,
                                                   const float4* __restrict__ tin,
                                                   float4* __restrict__ out) {
    __shared__ float As[128 * 36];  // 128 rows x 32 k (+4 pad)
    __shared__ float Ws[32 * 68];   // 32 k x 64 cols (+4 pad)
    __shared__ float s_sc[D], s_mn[D], s_bt[D], s_ro[D];
    int tid = threadIdx.x;
    if (tid < D) {
        const float inv = 1.0f / (float)N_NODES;
        float mu = g_sum[2][tid] * inv;
        float var = g_sq[2][tid] * inv - mu * mu;
        float ro = g_ro[2][tid];
        s_sc[tid] = gamma[2 * D + tid] * rsqrtf(var + BN_EPS);
        s_mn[tid] = ro + mu;
        s_bt[tid] = beta[2 * D + tid];
        s_ro[tid] = ro;
    }
    __syncthreads();

    int row0 = blockIdx.x * 128;
    int cg = tid & 15;    // column group: cols cg*4 .. cg*4+3
    int rg = tid >> 4;    // row group: rows rg + 16*j
    const float4* W4 = (const float4*)W;
    const float4* sc4 = (const float4*)s_sc;
    const float4* mn4 = (const float4*)s_mn;
    const float4* bt4 = (const float4*)s_bt;
    const float4* ro4 = (const float4*)s_ro;
    u64 acc2[8][2];
    u64 z = pack2(0.f);
#pragma unroll
    for (int j = 0; j < 8; j++) { acc2[j][0] = z; acc2[j][1] = z; }

    for (int kk = 0; kk < 4; kk++) {
        // stage A chunk with fused (t+ro-mean)*scale+beta, relu
#pragma unroll
        for (int it = 0; it < 4; it++) {
            int lin = tid + it * 256;
            int r = lin >> 3;
            int kc = lin & 7;
            int grow = row0 + r;
            float4 a = (grow < N_NODES) ? tin[grow * F4 + kk * 8 + kc]
                                        : make_float4(0.f, 0.f, 0.f, 0.f);
            a = normf(a, ro4[kk * 8 + kc], mn4[kk * 8 + kc], sc4[kk * 8 + kc], bt4[kk * 8 + kc]);
            *(float4*)&As[r * 36 + kc * 4] = a;
        }
        // stage W chunk
#pragma unroll
        for (int it = 0; it < 2; it++) {
            int lin = tid + it * 256;
            int k = lin >> 4;
            int c4 = lin & 15;
            *(float4*)&Ws[k * 68 + c4 * 4] = W4[(kk * 32 + k) * 16 + c4];
        }
        __syncthreads();
#pragma unroll
        for (int k4 = 0; k4 < 8; k4++) {
            u64 w[4][2];
#pragma unroll
            for (int kq = 0; kq < 4; kq++) {
                const u64* wp = (const u64*)&Ws[(k4 * 4 + kq) * 68 + cg * 4];
                w[kq][0] = wp[0];
                w[kq][1] = wp[1];
            }
#pragma unroll
            for (int j = 0; j < 8; j++) {
                float4 av = *(const float4*)&As[(rg + 16 * j) * 36 + k4 * 4];
                u64 a0 = pack2(av.x), a1 = pack2(av.y), a2 = pack2(av.z), a3 = pack2(av.w);
                ffma2(acc2[j][0], a0, w[0][0]); ffma2(acc2[j][1], a0, w[0][1]);
                ffma2(acc2[j][0], a1, w[1][0]); ffma2(acc2[j][1], a1, w[1][1]);
                ffma2(acc2[j][0], a2, w[2][0]); ffma2(acc2[j][1], a2, w[2][1]);
                ffma2(acc2[j][0], a3, w[3][0]); ffma2(acc2[j][1], a3, w[3][1]);
            }
        }
        __syncthreads();
    }
    float4 bb = ((const float4*)b)[cg];
#pragma unroll
    for (int j = 0; j < 8; j++) {
        int grow = row0 + rg + 16 * j;
        if (grow < N_NODES) {
            float2 p0 = *(float2*)&acc2[j][0];
            float2 p1 = *(float2*)&acc2[j][1];
            float4 o;
            o.x = p0.x + bb.x;
            o.y = p0.y + bb.y;
            o.z = p1.x + bb.z;
            o.w = p1.y + bb.w;
            out[grow * 16 + cg] = o;
        }
    }
}

// ---------------- launch ----------------
extern "C" void kernel_launch(void* const* d_in, const int* in_sizes, int n_in,
                              void* d_out, int out_size) {
    (void)in_sizes; (void)n_in; (void)out_size;
    const float* x = (const float*)d_in[0];
    const int* ei = (const int*)d_in[1];      // int32 per harness dtype table
    const float* gamma = (const float*)d_in[2];
    const float* beta = (const float*)d_in[3];
    const float* W = (const float*)d_in[4];
    const float* b = (const float*)d_in[5];
    float4* out = (float4*)d_out;

    const int WIDE = 1184;  // 8 * 148 SMs
    const int EV = (N_EDGES / 4 + 255) / 256;

    zero_kernel<<<(N_NODES + 255) / 256, 256>>>();                                   // 1
    hist_kernel<<<EV, 256>>>(ei);                                                    // 2
    scan_kernel<<<1, 1024>>>();                                                      // 3
    fill_kernel<<<EV, 256>>>(ei);                                                    // 4
    combine_kernel<false><<<WIDE, 256>>>(0, (const float4*)x, g_bufA, gamma, beta);  // 5
    combine_kernel<true><<<WIDE, 256>>>(1, (const float4*)g_bufA, g_bufB, gamma, beta); // 6 (ncu slot)
    combine_kernel<true><<<WIDE, 256>>>(2, (const float4*)g_bufB, g_bufA, gamma, beta); // 7
    gemm_kernel<<<(N_NODES + 127) / 128, 256>>>(W, b, gamma, beta,
                                                (const float4*)g_bufA, out);         // 8
}

// round 5
// speedup vs baseline: 21.2095x; 21.2095x over previous
#include <cuda_runtime.h>

#define N_NODES 100000
#define N_EDGES 1600000
#define D 128
#define F4 32          // float4 per row
#define D_OUT 64
#define BN_EPS 1e-5f

// ---------------- static device scratch (no allocations allowed) ----------------
__device__ int g_cnt[N_NODES];
__device__ int g_rowptr[N_NODES + 1];
__device__ int g_fill[N_NODES];
__device__ int g_col[N_EDGES];
__device__ float4 g_h[N_NODES * F4];     // current node features (post-layer)
__device__ float4 g_tmp[N_NODES * F4];   // pre-BN combined features (incl. readout)
__device__ __align__(16) float g_sum[3][D];
__device__ __align__(16) float g_sq[3][D];
__device__ __align__(16) float g_ro[3][D];      // readout per layer (colsum of h fed into layer)
__device__ __align__(16) float g_scale[3][D];   // gamma * rsqrt(var+eps)
__device__ __align__(16) float g_mean[3][D];    // mean of stored tmp values (incl. readout)
__device__ __align__(16) float g_beta[3][D];

// ---------------- init ----------------
__global__ void zero_kernel() {
    int i = blockIdx.x * 256 + threadIdx.x;
    if (i < N_NODES) g_cnt[i] = 0;
    if (i < 3 * D) {
        (&g_sum[0][0])[i] = 0.f;
        (&g_sq[0][0])[i]  = 0.f;
        (&g_ro[0][0])[i]  = 0.f;
    }
}

// ---------------- CSR build (edge_index delivered as int32 by the harness) ----------------
__global__ void hist_kernel(const int* __restrict__ ei) {
    int t = blockIdx.x * 256 + threadIdx.x;
    if (t < N_EDGES / 4) {
        int4 d4 = ((const int4*)ei)[t];      // dst = edge_index[0]
        atomicAdd(&g_cnt[d4.x], 1);
        atomicAdd(&g_cnt[d4.y], 1);
        atomicAdd(&g_cnt[d4.z], 1);
        atomicAdd(&g_cnt[d4.w], 1);
    }
}

// single-block scan, 1024 threads x 8 items
__global__ void scan_kernel() {
    __shared__ int warp_sums[32];
    __shared__ int s_carry;
    int tid = threadIdx.x;
    int lane = tid & 31, wid = tid >> 5;
    if (tid == 0) s_carry = 0;
    __syncthreads();
    const int CHUNK = 1024 * 8;
    for (int base = 0; base < N_NODES; base += CHUNK) {
        int idx0 = base + tid * 8;
        int v[8], pre[8];
        int run = 0;
#pragma unroll
        for (int k = 0; k < 8; k++) {
            int i = idx0 + k;
            v[k] = (i < N_NODES) ? g_cnt[i] : 0;
            run += v[k];
            pre[k] = run;                    // inclusive within thread
        }
        int tsum = run;
        int x = tsum;
#pragma unroll
        for (int dsh = 1; dsh < 32; dsh <<= 1) {
            int y = __shfl_up_sync(0xffffffffu, x, dsh);
            if (lane >= dsh) x += y;
        }
        if (lane == 31) warp_sums[wid] = x;
        __syncthreads();
        if (wid == 0) {
            int w = warp_sums[lane];
#pragma unroll
            for (int dsh = 1; dsh < 32; dsh <<= 1) {
                int y = __shfl_up_sync(0xffffffffu, w, dsh);
                if (lane >= dsh) w += y;
            }
            warp_sums[lane] = w;
        }
        __syncthreads();
        int carry = s_carry;
        int off = carry + (wid > 0 ? warp_sums[wid - 1] : 0) + (x - tsum);
#pragma unroll
        for (int k = 0; k < 8; k++) {
            int i = idx0 + k;
            if (i < N_NODES) {
                int ex = off + (pre[k] - v[k]);  // exclusive prefix
                g_rowptr[i] = ex;
                g_fill[i] = ex;
            }
        }
        __syncthreads();
        if (tid == 0) s_carry = carry + warp_sums[31];
        __syncthreads();
    }
    if (threadIdx.x == 0) g_rowptr[N_NODES] = s_carry;  // == N_EDGES
}

__global__ void fill_kernel(const int* __restrict__ ei) {
    int t = blockIdx.x * 256 + threadIdx.x;
    if (t < N_EDGES / 4) {
        int4 d4 = ((const int4*)ei)[t];
        int4 s4 = ((const int4*)(ei + N_EDGES))[t];
        int p0 = atomicAdd(&g_fill[d4.x], 1);
        int p1 = atomicAdd(&g_fill[d4.y], 1);
        int p2 = atomicAdd(&g_fill[d4.z], 1);
        int p3 = atomicAdd(&g_fill[d4.w], 1);
        g_col[p0] = s4.x;
        g_col[p1] = s4.y;
        g_col[p2] = s4.z;
        g_col[p3] = s4.w;
    }
}

// ---------------- column sum of input x (readout for layer 0) ----------------
__global__ void __launch_bounds__(256) colsum_kernel(const float4* __restrict__ in) {
    __shared__ float s[D];
    int fg = threadIdx.x & 31;
    int t = blockIdx.x * 256 + threadIdx.x;
    int stride = gridDim.x * 256;
    float4 ls = make_float4(0.f, 0.f, 0.f, 0.f);
    for (int idx = t; idx < N_NODES * F4; idx += stride) {
        float4 v = in[idx];
        ls.x += v.x; ls.y += v.y; ls.z += v.z; ls.w += v.w;
    }
    if (threadIdx.x < D) s[threadIdx.x] = 0.f;
    __syncthreads();
    int f = fg * 4;
    atomicAdd(&s[f + 0], ls.x);
    atomicAdd(&s[f + 1], ls.y);
    atomicAdd(&s[f + 2], ls.z);
    atomicAdd(&s[f + 3], ls.w);
    __syncthreads();
    if (threadIdx.x < D) atomicAdd(&g_ro[0][threadIdx.x], s[threadIdx.x]);
}

// ---------------- combine: h + CSR-gathered agg + readout; accumulate BN stats ----------------
// 4-edge unroll: batch 4 col loads + 4 row loads before the (strictly in-order) accumulate.
__global__ void __launch_bounds__(256) combine_kernel(int layer, const float4* __restrict__ xin) {
    __shared__ float ssum[D], ssq[D];
    const float4* __restrict__ hin = (layer == 0) ? xin : (const float4*)g_h;
    int lane = threadIdx.x & 31;
    int gw = (blockIdx.x * 256 + threadIdx.x) >> 5;
    int nw = (gridDim.x * 256) >> 5;
    float4 ro = ((const float4*)&g_ro[layer][0])[lane];
    float4 ls = make_float4(0.f, 0.f, 0.f, 0.f);
    float4 lq = make_float4(0.f, 0.f, 0.f, 0.f);
    for (int i = gw; i < N_NODES; i += nw) {
        int beg = g_rowptr[i];
        int end = g_rowptr[i + 1];
        float4 a = hin[i * F4 + lane];
        int e = beg;
        for (; e + 3 < end; e += 4) {
            int j0 = g_col[e];
            int j1 = g_col[e + 1];
            int j2 = g_col[e + 2];
            int j3 = g_col[e + 3];
            float4 v0 = hin[j0 * F4 + lane];
            float4 v1 = hin[j1 * F4 + lane];
            float4 v2 = hin[j2 * F4 + lane];
            float4 v3 = hin[j3 * F4 + lane];
            a.x += v0.x; a.y += v0.y; a.z += v0.z; a.w += v0.w;
            a.x += v1.x; a.y += v1.y; a.z += v1.z; a.w += v1.w;
            a.x += v2.x; a.y += v2.y; a.z += v2.z; a.w += v2.w;
            a.x += v3.x; a.y += v3.y; a.z += v3.z; a.w += v3.w;
        }
        for (; e < end; e++) {
            int j = g_col[e];
            float4 v = hin[j * F4 + lane];
            a.x += v.x; a.y += v.y; a.z += v.z; a.w += v.w;
        }
        // stats on pre-readout values (avoids fp32 cancellation; var is shift-invariant)
        ls.x += a.x; ls.y += a.y; ls.z += a.z; ls.w += a.w;
        lq.x += a.x * a.x; lq.y += a.y * a.y; lq.z += a.z * a.z; lq.w += a.w * a.w;
        float4 tt;
        tt.x = a.x + ro.x; tt.y = a.y + ro.y; tt.z = a.z + ro.z; tt.w = a.w + ro.w;
        g_tmp[i * F4 + lane] = tt;
    }
    if (threadIdx.x < D) { ssum[threadIdx.x] = 0.f; ssq[threadIdx.x] = 0.f; }
    __syncthreads();
    int f = lane * 4;
    atomicAdd(&ssum[f + 0], ls.x); atomicAdd(&ssum[f + 1], ls.y);
    atomicAdd(&ssum[f + 2], ls.z); atomicAdd(&ssum[f + 3], ls.w);
    atomicAdd(&ssq[f + 0], lq.x);  atomicAdd(&ssq[f + 1], lq.y);
    atomicAdd(&ssq[f + 2], lq.z);  atomicAdd(&ssq[f + 3], lq.w);
    __syncthreads();
    if (threadIdx.x < D) {
        atomicAdd(&g_sum[layer][threadIdx.x], ssum[threadIdx.x]);
        atomicAdd(&g_sq[layer][threadIdx.x], ssq[threadIdx.x]);
    }
}

// ---------------- BN finalize: per-feature scale / mean / beta ----------------
__global__ void finalize_kernel(int layer, const float* __restrict__ gamma,
                                const float* __restrict__ beta) {
    int f = threadIdx.x;
    const float inv = 1.0f / (float)N_NODES;
    float mu = g_sum[layer][f] * inv;                       // mean of pre-readout values
    float var = g_sq[layer][f] * inv - mu * mu;             // shift-invariant variance
    g_scale[layer][f] = gamma[f] * rsqrtf(var + BN_EPS);
    g_mean[layer][f] = g_ro[layer][f] + mu;                 // mean of stored tmp values
    g_beta[layer][f] = beta[f];
}

// ---------------- normalize + relu: (tmp - mean)*scale + beta ; accumulate next readout ----------------
__global__ void __launch_bounds__(256) normalize_kernel(int layer) {
    __shared__ float s[D];
    int fg = threadIdx.x & 31;
    int t = blockIdx.x * 256 + threadIdx.x;
    int stride = gridDim.x * 256;
    float4 sc = ((const float4*)&g_scale[layer][0])[fg];
    float4 mn = ((const float4*)&g_mean[layer][0])[fg];
    float4 bt = ((const float4*)&g_beta[layer][0])[fg];
    float4 ls = make_float4(0.f, 0.f, 0.f, 0.f);
    for (int idx = t; idx < N_NODES * F4; idx += stride) {
        float4 v = g_tmp[idx];
        v.x = fmaxf(fmaf(v.x - mn.x, sc.x, bt.x), 0.f);
        v.y = fmaxf(fmaf(v.y - mn.y, sc.y, bt.y), 0.f);
        v.z = fmaxf(fmaf(v.z - mn.z, sc.z, bt.z), 0.f);
        v.w = fmaxf(fmaf(v.w - mn.w, sc.w, bt.w), 0.f);
        g_h[idx] = v;
        ls.x += v.x; ls.y += v.y; ls.z += v.z; ls.w += v.w;
    }
    if (threadIdx.x < D) s[threadIdx.x] = 0.f;
    __syncthreads();
    int f = fg * 4;
    atomicAdd(&s[f + 0], ls.x);
    atomicAdd(&s[f + 1], ls.y);
    atomicAdd(&s[f + 2], ls.z);
    atomicAdd(&s[f + 3], ls.w);
    __syncthreads();
    if (threadIdx.x < D) atomicAdd(&g_ro[layer + 1][threadIdx.x], s[threadIdx.x]);
}

// ---------------- final: fused (normalize+relu of layer2) @ W + b ----------------
// block: 256 threads, tile 128 rows x 64 cols; thread computes 8 rows x 4 cols
__global__ void __launch_bounds__(256) gemm_kernel(const float* __restrict__ W,
                                                   const float* __restrict__ b,
                                                   float4* __restrict__ out) {
    __shared__ float As[128 * 36];  // 128 rows x 32 k (+4 pad)
    __shared__ float Ws[32 * 68];   // 32 k x 64 cols (+4 pad)
    int tid = threadIdx.x;
    int row0 = blockIdx.x * 128;
    int cg = tid & 15;    // column group: cols cg*4 .. cg*4+3
    int rg = tid >> 4;    // row group: rows rg + 16*j
    const float4* W4 = (const float4*)W;
    const float4* sc4 = (const float4*)&g_scale[2][0];
    const float4* mn4 = (const float4*)&g_mean[2][0];
    const float4* bt4 = (const float4*)&g_beta[2][0];
    float4 acc[8];
#pragma unroll
    for (int j = 0; j < 8; j++) acc[j] = make_float4(0.f, 0.f, 0.f, 0.f);

    for (int kk = 0; kk < 4; kk++) {
        // stage A chunk with fused (x-mean)*scale+beta, relu
#pragma unroll
        for (int it = 0; it < 4; it++) {
            int lin = tid + it * 256;
            int r = lin >> 3;
            int kc = lin & 7;
            int grow = row0 + r;
            float4 a = (grow < N_NODES) ? g_tmp[grow * F4 + kk * 8 + kc]
                                        : make_float4(0.f, 0.f, 0.f, 0.f);
            float4 s = sc4[kk * 8 + kc];
            float4 m = mn4[kk * 8 + kc];
            float4 t = bt4[kk * 8 + kc];
            a.x = fmaxf(fmaf(a.x - m.x, s.x, t.x), 0.f);
            a.y = fmaxf(fmaf(a.y - m.y, s.y, t.y), 0.f);
            a.z = fmaxf(fmaf(a.z - m.z, s.z, t.z), 0.f);
            a.w = fmaxf(fmaf(a.w - m.w, s.w, t.w), 0.f);
            *(float4*)&As[r * 36 + kc * 4] = a;
        }
        // stage W chunk
#pragma unroll
        for (int it = 0; it < 2; it++) {
            int lin = tid + it * 256;
            int k = lin >> 4;
            int c4 = lin & 15;
            *(float4*)&Ws[k * 68 + c4 * 4] = W4[(kk * 32 + k) * 16 + c4];
        }
        __syncthreads();
#pragma unroll
        for (int k4 = 0; k4 < 8; k4++) {
            float4 w0 = *(const float4*)&Ws[(k4 * 4 + 0) * 68 + cg * 4];
            float4 w1 = *(const float4*)&Ws[(k4 * 4 + 1) * 68 + cg * 4];
            float4 w2 = *(const float4*)&Ws[(k4 * 4 + 2) * 68 + cg * 4];
            float4 w3 = *(const float4*)&Ws[(k4 * 4 + 3) * 68 + cg * 4];
#pragma unroll
            for (int j = 0; j < 8; j++) {
                float4 a = *(const float4*)&As[(rg + 16 * j) * 36 + k4 * 4];
                acc[j].x = fmaf(a.x, w0.x, fmaf(a.y, w1.x, fmaf(a.z, w2.x, fmaf(a.w, w3.x, acc[j].x))));
                acc[j].y = fmaf(a.x, w0.y, fmaf(a.y, w1.y, fmaf(a.z, w2.y, fmaf(a.w, w3.y, acc[j].y))));
                acc[j].z = fmaf(a.x, w0.z, fmaf(a.y, w1.z, fmaf(a.z, w2.z, fmaf(a.w, w3.z, acc[j].z))));
                acc[j].w = fmaf(a.x, w0.w, fmaf(a.y, w1.w, fmaf(a.z, w2.w, fmaf(a.w, w3.w, acc[j].w))));
            }
        }
        __syncthreads();
    }
    float4 bb = ((const float4*)b)[cg];
#pragma unroll
    for (int j = 0; j < 8; j++) {
        int grow = row0 + rg + 16 * j;
        if (grow < N_NODES) {
            float4 o;
            o.x = acc[j].x + bb.x;
            o.y = acc[j].y + bb.y;
            o.z = acc[j].z + bb.z;
            o.w = acc[j].w + bb.w;
            out[grow * 16 + cg] = o;
        }
    }
}

// ---------------- launch ----------------
extern "C" void kernel_launch(void* const* d_in, const int* in_sizes, int n_in,
                              void* d_out, int out_size) {
    (void)in_sizes; (void)n_in; (void)out_size;
    const float* x = (const float*)d_in[0];
    const int* ei = (const int*)d_in[1];      // int32 per harness dtype table
    const float* gamma = (const float*)d_in[2];
    const float* beta = (const float*)d_in[3];
    const float* W = (const float*)d_in[4];
    const float* b = (const float*)d_in[5];
    float4* out = (float4*)d_out;

    const int WIDE = 1184;  // 8 * 148 SMs
    const int EV = (N_EDGES / 4 + 255) / 256;

    zero_kernel<<<(N_NODES + 255) / 256, 256>>>();
    hist_kernel<<<EV, 256>>>(ei);
    scan_kernel<<<1, 1024>>>();
    fill_kernel<<<EV, 256>>>(ei);
    colsum_kernel<<<WIDE, 256>>>((const float4*)x);

    for (int layer = 0; layer < 3; layer++) {
        combine_kernel<<<WIDE, 256>>>(layer, (const float4*)x);
        finalize_kernel<<<1, D>>>(layer, gamma + layer * D, beta + layer * D);
        if (layer < 2) normalize_kernel<<<WIDE, 256>>>(layer);
    }
    gemm_kernel<<<(N_NODES + 127) / 128, 256>>>(W, b, out);
}

// round 6
// speedup vs baseline: 21.7337x; 1.0247x over previous
#include <cuda_runtime.h>

#define N_NODES 100000
#define N_EDGES 1600000
#define D 128
#define F4 32          // float4 per row
#define D_OUT 64
#define BN_EPS 1e-5f

// ---------------- static device scratch (no allocations allowed) ----------------
__device__ int g_cnt[N_NODES];
__device__ int g_rowptr[N_NODES + 1];
__device__ int g_fill[N_NODES];
__device__ int g_col[N_EDGES];
__device__ float4 g_h[N_NODES * F4];     // normalized features (layer input)
__device__ float4 g_tmp[N_NODES * F4];   // pre-BN, PRE-READOUT combined features
__device__ __align__(16) float g_sum[3][D];   // colsum of pre-readout a
__device__ __align__(16) float g_sq[3][D];    // colsum of a^2
__device__ __align__(16) float g_ro[3][D];    // readout: colsum of input fed into layer L

// ---------------- init ----------------
__global__ void zero_kernel() {
    int i = blockIdx.x * 256 + threadIdx.x;
    if (i < N_NODES) g_cnt[i] = 0;
    if (i < 3 * D) {
        (&g_sum[0][0])[i] = 0.f;
        (&g_sq[0][0])[i]  = 0.f;
        (&g_ro[0][0])[i]  = 0.f;
    }
}

// ---------------- CSR build (edge_index delivered as int32 by the harness) ----------------
// 8 edges per thread (2 x int4) for MLP
__global__ void hist_kernel(const int* __restrict__ ei) {
    int t = blockIdx.x * 256 + threadIdx.x;
    int base = t * 2;
    if (base < N_EDGES / 4) {
        int4 a = ((const int4*)ei)[base];
        int4 b = ((const int4*)ei)[base + 1];
        atomicAdd(&g_cnt[a.x], 1); atomicAdd(&g_cnt[a.y], 1);
        atomicAdd(&g_cnt[a.z], 1); atomicAdd(&g_cnt[a.w], 1);
        atomicAdd(&g_cnt[b.x], 1); atomicAdd(&g_cnt[b.y], 1);
        atomicAdd(&g_cnt[b.z], 1); atomicAdd(&g_cnt[b.w], 1);
    }
}

// single-block scan, 1024 threads x 8 items
__global__ void scan_kernel() {
    __shared__ int warp_sums[32];
    __shared__ int s_carry;
    int tid = threadIdx.x;
    int lane = tid & 31, wid = tid >> 5;
    if (tid == 0) s_carry = 0;
    __syncthreads();
    const int CHUNK = 1024 * 8;
    for (int base = 0; base < N_NODES; base += CHUNK) {
        int idx0 = base + tid * 8;
        int v[8], pre[8];
        int run = 0;
#pragma unroll
        for (int k = 0; k < 8; k++) {
            int i = idx0 + k;
            v[k] = (i < N_NODES) ? g_cnt[i] : 0;
            run += v[k];
            pre[k] = run;                    // inclusive within thread
        }
        int tsum = run;
        int x = tsum;
#pragma unroll
        for (int dsh = 1; dsh < 32; dsh <<= 1) {
            int y = __shfl_up_sync(0xffffffffu, x, dsh);
            if (lane >= dsh) x += y;
        }
        if (lane == 31) warp_sums[wid] = x;
        __syncthreads();
        if (wid == 0) {
            int w = warp_sums[lane];
#pragma unroll
            for (int dsh = 1; dsh < 32; dsh <<= 1) {
                int y = __shfl_up_sync(0xffffffffu, w, dsh);
                if (lane >= dsh) w += y;
            }
            warp_sums[lane] = w;
        }
        __syncthreads();
        int carry = s_carry;
        int off = carry + (wid > 0 ? warp_sums[wid - 1] : 0) + (x - tsum);
#pragma unroll
        for (int k = 0; k < 8; k++) {
            int i = idx0 + k;
            if (i < N_NODES) {
                int ex = off + (pre[k] - v[k]);  // exclusive prefix
                g_rowptr[i] = ex;
                g_fill[i] = ex;
            }
        }
        __syncthreads();
        if (tid == 0) s_carry = carry + warp_sums[31];
        __syncthreads();
    }
    if (threadIdx.x == 0) g_rowptr[N_NODES] = s_carry;  // == N_EDGES
}

__global__ void fill_kernel(const int* __restrict__ ei) {
    int t = blockIdx.x * 256 + threadIdx.x;
    int base = t * 2;
    if (base < N_EDGES / 4) {
        int4 d0 = ((const int4*)ei)[base];
        int4 d1 = ((const int4*)ei)[base + 1];
        int4 s0 = ((const int4*)(ei + N_EDGES))[base];
        int4 s1 = ((const int4*)(ei + N_EDGES))[base + 1];
        int p0 = atomicAdd(&g_fill[d0.x], 1);
        int p1 = atomicAdd(&g_fill[d0.y], 1);
        int p2 = atomicAdd(&g_fill[d0.z], 1);
        int p3 = atomicAdd(&g_fill[d0.w], 1);
        g_col[p0] = s0.x; g_col[p1] = s0.y; g_col[p2] = s0.z; g_col[p3] = s0.w;
        int q0 = atomicAdd(&g_fill[d1.x], 1);
        int q1 = atomicAdd(&g_fill[d1.y], 1);
        int q2 = atomicAdd(&g_fill[d1.z], 1);
        int q3 = atomicAdd(&g_fill[d1.w], 1);
        g_col[q0] = s1.x; g_col[q1] = s1.y; g_col[q2] = s1.z; g_col[q3] = s1.w;
    }
}

// ---------------- combine: self + CSR-gathered agg (pre-readout); stats + readout ----------------
// 8-edge unroll: batch 8 col loads + 8 row loads before the (strictly in-order) accumulate.
__global__ void __launch_bounds__(256) combine_kernel(int layer, const float4* __restrict__ xin) {
    __shared__ float ssum[D], ssq[D], sro[D];
    const float4* __restrict__ hin = (layer == 0) ? xin : (const float4*)g_h;
    int tid = threadIdx.x;
    if (tid < D) { ssum[tid] = 0.f; ssq[tid] = 0.f; sro[tid] = 0.f; }
    __syncthreads();
    int lane = tid & 31;
    int gw = (blockIdx.x * 256 + tid) >> 5;
    int nw = (gridDim.x * 256) >> 5;
    float4 ls = make_float4(0.f, 0.f, 0.f, 0.f);
    float4 lq = make_float4(0.f, 0.f, 0.f, 0.f);
    float4 lr = make_float4(0.f, 0.f, 0.f, 0.f);
    for (int i = gw; i < N_NODES; i += nw) {
        int beg = g_rowptr[i];
        int end = g_rowptr[i + 1];
        float4 a = hin[i * F4 + lane];
        // readout for this layer = colsum of layer input (self rows cover every node once)
        lr.x += a.x; lr.y += a.y; lr.z += a.z; lr.w += a.w;
        int e = beg;
        for (; e + 7 < end; e += 8) {
            int j0 = g_col[e];
            int j1 = g_col[e + 1];
            int j2 = g_col[e + 2];
            int j3 = g_col[e + 3];
            int j4 = g_col[e + 4];
            int j5 = g_col[e + 5];
            int j6 = g_col[e + 6];
            int j7 = g_col[e + 7];
            float4 v0 = hin[j0 * F4 + lane];
            float4 v1 = hin[j1 * F4 + lane];
            float4 v2 = hin[j2 * F4 + lane];
            float4 v3 = hin[j3 * F4 + lane];
            float4 v4 = hin[j4 * F4 + lane];
            float4 v5 = hin[j5 * F4 + lane];
            float4 v6 = hin[j6 * F4 + lane];
            float4 v7 = hin[j7 * F4 + lane];
            a.x += v0.x; a.y += v0.y; a.z += v0.z; a.w += v0.w;
            a.x += v1.x; a.y += v1.y; a.z += v1.z; a.w += v1.w;
            a.x += v2.x; a.y += v2.y; a.z += v2.z; a.w += v2.w;
            a.x += v3.x; a.y += v3.y; a.z += v3.z; a.w += v3.w;
            a.x += v4.x; a.y += v4.y; a.z += v4.z; a.w += v4.w;
            a.x += v5.x; a.y += v5.y; a.z += v5.z; a.w += v5.w;
            a.x += v6.x; a.y += v6.y; a.z += v6.z; a.w += v6.w;
            a.x += v7.x; a.y += v7.y; a.z += v7.z; a.w += v7.w;
        }
        for (; e + 3 < end; e += 4) {
            int j0 = g_col[e];
            int j1 = g_col[e + 1];
            int j2 = g_col[e + 2];
            int j3 = g_col[e + 3];
            float4 v0 = hin[j0 * F4 + lane];
            float4 v1 = hin[j1 * F4 + lane];
            float4 v2 = hin[j2 * F4 + lane];
            float4 v3 = hin[j3 * F4 + lane];
            a.x += v0.x; a.y += v0.y; a.z += v0.z; a.w += v0.w;
            a.x += v1.x; a.y += v1.y; a.z += v1.z; a.w += v1.w;
            a.x += v2.x; a.y += v2.y; a.z += v2.z; a.w += v2.w;
            a.x += v3.x; a.y += v3.y; a.z += v3.z; a.w += v3.w;
        }
        for (; e < end; e++) {
            int j = g_col[e];
            float4 v = hin[j * F4 + lane];
            a.x += v.x; a.y += v.y; a.z += v.z; a.w += v.w;
        }
        // stats on pre-readout values (variance is shift-invariant)
        ls.x += a.x; ls.y += a.y; ls.z += a.z; ls.w += a.w;
        lq.x += a.x * a.x; lq.y += a.y * a.y; lq.z += a.z * a.z; lq.w += a.w * a.w;
        g_tmp[i * F4 + lane] = a;              // pre-readout; consumer adds ro
    }
    int f = lane * 4;
    atomicAdd(&ssum[f + 0], ls.x); atomicAdd(&ssum[f + 1], ls.y);
    atomicAdd(&ssum[f + 2], ls.z); atomicAdd(&ssum[f + 3], ls.w);
    atomicAdd(&ssq[f + 0], lq.x);  atomicAdd(&ssq[f + 1], lq.y);
    atomicAdd(&ssq[f + 2], lq.z);  atomicAdd(&ssq[f + 3], lq.w);
    atomicAdd(&sro[f + 0], lr.x);  atomicAdd(&sro[f + 1], lr.y);
    atomicAdd(&sro[f + 2], lr.z);  atomicAdd(&sro[f + 3], lr.w);
    __syncthreads();
    if (tid < D) {
        atomicAdd(&g_sum[layer][tid], ssum[tid]);
        atomicAdd(&g_sq[layer][tid], ssq[tid]);
        atomicAdd(&g_ro[layer][tid], sro[tid]);
    }
}

// ---------------- normalize + relu: ((tmp + ro) - mean)*scale + beta ----------------
// BN params computed in per-block prelude (replaces finalize kernel; same arithmetic).
__global__ void __launch_bounds__(256) normalize_kernel(int layer,
                                                        const float* __restrict__ gamma,
                                                        const float* __restrict__ beta) {
    __shared__ float s_sc[D], s_mn[D], s_bt[D], s_ro[D];
    int tid = threadIdx.x;
    if (tid < D) {
        const float inv = 1.0f / (float)N_NODES;
        float mu = g_sum[layer][tid] * inv;
        float var = g_sq[layer][tid] * inv - mu * mu;     // shift-invariant variance
        float ro = g_ro[layer][tid];
        s_sc[tid] = gamma[layer * D + tid] * rsqrtf(var + BN_EPS);
        s_mn[tid] = ro + mu;                              // mean of (a + ro) values
        s_bt[tid] = beta[layer * D + tid];
        s_ro[tid] = ro;
    }
    __syncthreads();
    int fg = tid & 31;
    float4 sc = ((const float4*)s_sc)[fg];
    float4 mn = ((const float4*)s_mn)[fg];
    float4 bt = ((const float4*)s_bt)[fg];
    float4 ro = ((const float4*)s_ro)[fg];
    int t = blockIdx.x * 256 + tid;
    int stride = gridDim.x * 256;
    for (int idx = t; idx < N_NODES * F4; idx += stride) {
        float4 v = g_tmp[idx];
        v.x = fmaxf(fmaf((v.x + ro.x) - mn.x, sc.x, bt.x), 0.f);
        v.y = fmaxf(fmaf((v.y + ro.y) - mn.y, sc.y, bt.y), 0.f);
        v.z = fmaxf(fmaf((v.z + ro.z) - mn.z, sc.z, bt.z), 0.f);
        v.w = fmaxf(fmaf((v.w + ro.w) - mn.w, sc.w, bt.w), 0.f);
        g_h[idx] = v;
    }
}

// ---------------- final: fused (normalize+relu of layer2) @ W + b ----------------
// block: 256 threads, tile 128 rows x 64 cols; thread computes 8 rows x 4 cols
__global__ void __launch_bounds__(256) gemm_kernel(const float* __restrict__ W,
                                                   const float* __restrict__ b,
                                                   const float* __restrict__ gamma,
                                                   const float* __restrict__ beta,
                                                   float4* __restrict__ out) {
    __shared__ float As[128 * 36];  // 128 rows x 32 k (+4 pad)
    __shared__ float Ws[32 * 68];   // 32 k x 64 cols (+4 pad)
    __shared__ float s_sc[D], s_mn[D], s_bt[D], s_ro[D];
    int tid = threadIdx.x;
    if (tid < D) {
        const float inv = 1.0f / (float)N_NODES;
        float mu = g_sum[2][tid] * inv;
        float var = g_sq[2][tid] * inv - mu * mu;
        float ro = g_ro[2][tid];
        s_sc[tid] = gamma[2 * D + tid] * rsqrtf(var + BN_EPS);
        s_mn[tid] = ro + mu;
        s_bt[tid] = beta[2 * D + tid];
        s_ro[tid] = ro;
    }
    __syncthreads();
    int row0 = blockIdx.x * 128;
    int cg = tid & 15;    // column group: cols cg*4 .. cg*4+3
    int rg = tid >> 4;    // row group: rows rg + 16*j
    const float4* W4 = (const float4*)W;
    const float4* sc4 = (const float4*)s_sc;
    const float4* mn4 = (const float4*)s_mn;
    const float4* bt4 = (const float4*)s_bt;
    const float4* ro4 = (const float4*)s_ro;
    float4 acc[8];
#pragma unroll
    for (int j = 0; j < 8; j++) acc[j] = make_float4(0.f, 0.f, 0.f, 0.f);

    for (int kk = 0; kk < 4; kk++) {
        // stage A chunk with fused ((x+ro)-mean)*scale+beta, relu
#pragma unroll
        for (int it = 0; it < 4; it++) {
            int lin = tid + it * 256;
            int r = lin >> 3;
            int kc = lin & 7;
            int grow = row0 + r;
            float4 a = (grow < N_NODES) ? g_tmp[grow * F4 + kk * 8 + kc]
                                        : make_float4(0.f, 0.f, 0.f, 0.f);
            float4 s = sc4[kk * 8 + kc];
            float4 m = mn4[kk * 8 + kc];
            float4 t = bt4[kk * 8 + kc];
            float4 r4 = ro4[kk * 8 + kc];
            a.x = fmaxf(fmaf((a.x + r4.x) - m.x, s.x, t.x), 0.f);
            a.y = fmaxf(fmaf((a.y + r4.y) - m.y, s.y, t.y), 0.f);
            a.z = fmaxf(fmaf((a.z + r4.z) - m.z, s.z, t.z), 0.f);
            a.w = fmaxf(fmaf((a.w + r4.w) - m.w, s.w, t.w), 0.f);
            *(float4*)&As[r * 36 + kc * 4] = a;
        }
        // stage W chunk
#pragma unroll
        for (int it = 0; it < 2; it++) {
            int lin = tid + it * 256;
            int k = lin >> 4;
            int c4 = lin & 15;
            *(float4*)&Ws[k * 68 + c4 * 4] = W4[(kk * 32 + k) * 16 + c4];
        }
        __syncthreads();
#pragma unroll
        for (int k4 = 0; k4 < 8; k4++) {
            float4 w0 = *(const float4*)&Ws[(k4 * 4 + 0) * 68 + cg * 4];
            float4 w1 = *(const float4*)&Ws[(k4 * 4 + 1) * 68 + cg * 4];
            float4 w2 = *(const float4*)&Ws[(k4 * 4 + 2) * 68 + cg * 4];
            float4 w3 = *(const float4*)&Ws[(k4 * 4 + 3) * 68 + cg * 4];
#pragma unroll
            for (int j = 0; j < 8; j++) {
                float4 a = *(const float4*)&As[(rg + 16 * j) * 36 + k4 * 4];
                acc[j].x = fmaf(a.x, w0.x, fmaf(a.y, w1.x, fmaf(a.z, w2.x, fmaf(a.w, w3.x, acc[j].x))));
                acc[j].y = fmaf(a.x, w0.y, fmaf(a.y, w1.y, fmaf(a.z, w2.y, fmaf(a.w, w3.y, acc[j].y))));
                acc[j].z = fmaf(a.x, w0.z, fmaf(a.y, w1.z, fmaf(a.z, w2.z, fmaf(a.w, w3.z, acc[j].z))));
                acc[j].w = fmaf(a.x, w0.w, fmaf(a.y, w1.w, fmaf(a.z, w2.w, fmaf(a.w, w3.w, acc[j].w))));
            }
        }
        __syncthreads();
    }
    float4 bb = ((const float4*)b)[cg];
#pragma unroll
    for (int j = 0; j < 8; j++) {
        int grow = row0 + rg + 16 * j;
        if (grow < N_NODES) {
            float4 o;
            o.x = acc[j].x + bb.x;
            o.y = acc[j].y + bb.y;
            o.z = acc[j].z + bb.z;
            o.w = acc[j].w + bb.w;
            out[grow * 16 + cg] = o;
        }
    }
}

// ---------------- launch ----------------
extern "C" void kernel_launch(void* const* d_in, const int* in_sizes, int n_in,
                              void* d_out, int out_size) {
    (void)in_sizes; (void)n_in; (void)out_size;
    const float* x = (const float*)d_in[0];
    const int* ei = (const int*)d_in[1];      // int32 per harness dtype table
    const float* gamma = (const float*)d_in[2];
    const float* beta = (const float*)d_in[3];
    const float* W = (const float*)d_in[4];
    const float* b = (const float*)d_in[5];
    float4* out = (float4*)d_out;

    const int WIDE = 1184;  // 8 * 148 SMs
    const int EV8 = (N_EDGES / 8 + 255) / 256;

    zero_kernel<<<(N_NODES + 255) / 256, 256>>>();
    hist_kernel<<<EV8, 256>>>(ei);
    scan_kernel<<<1, 1024>>>();
    fill_kernel<<<EV8, 256>>>(ei);

    for (int layer = 0; layer < 3; layer++) {
        combine_kernel<<<WIDE, 256>>>(layer, (const float4*)x);
        if (layer < 2) normalize_kernel<<<WIDE, 256>>>(layer, gamma, beta);
    }
    gemm_kernel<<<(N_NODES + 127) / 128, 256>>>(W, b, gamma, beta, out);
}

// round 7
// speedup vs baseline: 24.6731x; 1.1352x over previous
#include <cuda_runtime.h>

#define N_NODES 100000
#define N_EDGES 1600000
#define D 128
#define F4 32          // float4 per row
#define D_OUT 64
#define BN_EPS 1e-5f

// ---------------- static device scratch (no allocations allowed) ----------------
__device__ int g_cnt[N_NODES];
__device__ int g_rowptr[N_NODES + 1];
__device__ int g_rank[N_EDGES];          // rank of edge within its dst bucket
__device__ int g_col[N_EDGES];
__device__ float4 g_h[N_NODES * F4];     // normalized features (layer input)
__device__ float4 g_tmp[N_NODES * F4];   // pre-BN, PRE-READOUT combined features
__device__ __align__(16) float g_sum[3][D];   // colsum of pre-readout a
__device__ __align__(16) float g_sq[3][D];    // colsum of a^2
__device__ __align__(16) float g_ro[3][D];    // readout: colsum of input fed into layer L

// ---------------- init ----------------
__global__ void zero_kernel() {
    int i = blockIdx.x * 256 + threadIdx.x;
    if (i < N_NODES) g_cnt[i] = 0;
    if (i < 3 * D) {
        (&g_sum[0][0])[i] = 0.f;
        (&g_sq[0][0])[i]  = 0.f;
        (&g_ro[0][0])[i]  = 0.f;
    }
}

// ---------------- CSR build (edge_index delivered as int32 by the harness) ----------------
// hist also records each edge's rank within its dst bucket (atomicAdd return value).
__global__ void hist_kernel(const int* __restrict__ ei) {
    int t = blockIdx.x * 256 + threadIdx.x;
    if (t < N_EDGES / 4) {
        int4 d4 = ((const int4*)ei)[t];      // dst = edge_index[0]
        int4 r;
        r.x = atomicAdd(&g_cnt[d4.x], 1);
        r.y = atomicAdd(&g_cnt[d4.y], 1);
        r.z = atomicAdd(&g_cnt[d4.z], 1);
        r.w = atomicAdd(&g_cnt[d4.w], 1);
        ((int4*)g_rank)[t] = r;
    }
}

// single-block scan, 1024 threads x 8 items
__global__ void scan_kernel() {
    __shared__ int warp_sums[32];
    __shared__ int s_carry;
    int tid = threadIdx.x;
    int lane = tid & 31, wid = tid >> 5;
    if (tid == 0) s_carry = 0;
    __syncthreads();
    const int CHUNK = 1024 * 8;
    for (int base = 0; base < N_NODES; base += CHUNK) {
        int idx0 = base + tid * 8;
        int v[8], pre[8];
        int run = 0;
#pragma unroll
        for (int k = 0; k < 8; k++) {
            int i = idx0 + k;
            v[k] = (i < N_NODES) ? g_cnt[i] : 0;
            run += v[k];
            pre[k] = run;                    // inclusive within thread
        }
        int tsum = run;
        int x = tsum;
#pragma unroll
        for (int dsh = 1; dsh < 32; dsh <<= 1) {
            int y = __shfl_up_sync(0xffffffffu, x, dsh);
            if (lane >= dsh) x += y;
        }
        if (lane == 31) warp_sums[wid] = x;
        __syncthreads();
        if (wid == 0) {
            int w = warp_sums[lane];
#pragma unroll
            for (int dsh = 1; dsh < 32; dsh <<= 1) {
                int y = __shfl_up_sync(0xffffffffu, w, dsh);
                if (lane >= dsh) w += y;
            }
            warp_sums[lane] = w;
        }
        __syncthreads();
        int carry = s_carry;
        int off = carry + (wid > 0 ? warp_sums[wid - 1] : 0) + (x - tsum);
#pragma unroll
        for (int k = 0; k < 8; k++) {
            int i = idx0 + k;
            if (i < N_NODES) {
                g_rowptr[i] = off + (pre[k] - v[k]);  // exclusive prefix
            }
        }
        __syncthreads();
        if (tid == 0) s_carry = carry + warp_sums[31];
        __syncthreads();
    }
    if (threadIdx.x == 0) g_rowptr[N_NODES] = s_carry;  // == N_EDGES
}

// atomic-free fill: pos = rowptr[dst] + rank
__global__ void fill_kernel(const int* __restrict__ ei) {
    int t = blockIdx.x * 256 + threadIdx.x;
    if (t < N_EDGES / 4) {
        int4 d4 = ((const int4*)ei)[t];
        int4 s4 = ((const int4*)(ei + N_EDGES))[t];
        int4 r4 = ((const int4*)g_rank)[t];
        int p0 = g_rowptr[d4.x] + r4.x;
        int p1 = g_rowptr[d4.y] + r4.y;
        int p2 = g_rowptr[d4.z] + r4.z;
        int p3 = g_rowptr[d4.w] + r4.w;
        g_col[p0] = s4.x;
        g_col[p1] = s4.y;
        g_col[p2] = s4.z;
        g_col[p3] = s4.w;
    }
}

// ---------------- combine: self + CSR-gathered agg (pre-readout); stats + readout ----------------
// 8-edge unroll: batch 8 col loads + 8 row loads (L2-only via __ldcg) before in-order accumulate.
__global__ void __launch_bounds__(256) combine_kernel(int layer, const float4* __restrict__ xin) {
    __shared__ float ssum[D], ssq[D], sro[D];
    const float4* __restrict__ hin = (layer == 0) ? xin : (const float4*)g_h;
    int tid = threadIdx.x;
    if (tid < D) { ssum[tid] = 0.f; ssq[tid] = 0.f; sro[tid] = 0.f; }
    __syncthreads();
    int lane = tid & 31;
    int gw = (blockIdx.x * 256 + tid) >> 5;
    int nw = (gridDim.x * 256) >> 5;
    float4 ls = make_float4(0.f, 0.f, 0.f, 0.f);
    float4 lq = make_float4(0.f, 0.f, 0.f, 0.f);
    float4 lr = make_float4(0.f, 0.f, 0.f, 0.f);
    for (int i = gw; i < N_NODES; i += nw) {
        int beg = g_rowptr[i];
        int end = g_rowptr[i + 1];
        float4 a = hin[i * F4 + lane];
        // readout for this layer = colsum of layer input (self rows cover every node once)
        lr.x += a.x; lr.y += a.y; lr.z += a.z; lr.w += a.w;
        int e = beg;
        for (; e + 7 < end; e += 8) {
            int j0 = g_col[e];
            int j1 = g_col[e + 1];
            int j2 = g_col[e + 2];
            int j3 = g_col[e + 3];
            int j4 = g_col[e + 4];
            int j5 = g_col[e + 5];
            int j6 = g_col[e + 6];
            int j7 = g_col[e + 7];
            float4 v0 = __ldcg(&hin[j0 * F4 + lane]);
            float4 v1 = __ldcg(&hin[j1 * F4 + lane]);
            float4 v2 = __ldcg(&hin[j2 * F4 + lane]);
            float4 v3 = __ldcg(&hin[j3 * F4 + lane]);
            float4 v4 = __ldcg(&hin[j4 * F4 + lane]);
            float4 v5 = __ldcg(&hin[j5 * F4 + lane]);
            float4 v6 = __ldcg(&hin[j6 * F4 + lane]);
            float4 v7 = __ldcg(&hin[j7 * F4 + lane]);
            a.x += v0.x; a.y += v0.y; a.z += v0.z; a.w += v0.w;
            a.x += v1.x; a.y += v1.y; a.z += v1.z; a.w += v1.w;
            a.x += v2.x; a.y += v2.y; a.z += v2.z; a.w += v2.w;
            a.x += v3.x; a.y += v3.y; a.z += v3.z; a.w += v3.w;
            a.x += v4.x; a.y += v4.y; a.z += v4.z; a.w += v4.w;
            a.x += v5.x; a.y += v5.y; a.z += v5.z; a.w += v5.w;
            a.x += v6.x; a.y += v6.y; a.z += v6.z; a.w += v6.w;
            a.x += v7.x; a.y += v7.y; a.z += v7.z; a.w += v7.w;
        }
        for (; e + 3 < end; e += 4) {
            int j0 = g_col[e];
            int j1 = g_col[e + 1];
            int j2 = g_col[e + 2];
            int j3 = g_col[e + 3];
            float4 v0 = __ldcg(&hin[j0 * F4 + lane]);
            float4 v1 = __ldcg(&hin[j1 * F4 + lane]);
            float4 v2 = __ldcg(&hin[j2 * F4 + lane]);
            float4 v3 = __ldcg(&hin[j3 * F4 + lane]);
            a.x += v0.x; a.y += v0.y; a.z += v0.z; a.w += v0.w;
            a.x += v1.x; a.y += v1.y; a.z += v1.z; a.w += v1.w;
            a.x += v2.x; a.y += v2.y; a.z += v2.z; a.w += v2.w;
            a.x += v3.x; a.y += v3.y; a.z += v3.z; a.w += v3.w;
        }
        for (; e < end; e++) {
            int j = g_col[e];
            float4 v = __ldcg(&hin[j * F4 + lane]);
            a.x += v.x; a.y += v.y; a.z += v.z; a.w += v.w;
        }
        // stats on pre-readout values (variance is shift-invariant)
        ls.x += a.x; ls.y += a.y; ls.z += a.z; ls.w += a.w;
        lq.x += a.x * a.x; lq.y += a.y * a.y; lq.z += a.z * a.z; lq.w += a.w * a.w;
        g_tmp[i * F4 + lane] = a;              // pre-readout; consumer adds ro
    }
    int f = lane * 4;
    atomicAdd(&ssum[f + 0], ls.x); atomicAdd(&ssum[f + 1], ls.y);
    atomicAdd(&ssum[f + 2], ls.z); atomicAdd(&ssum[f + 3], ls.w);
    atomicAdd(&ssq[f + 0], lq.x);  atomicAdd(&ssq[f + 1], lq.y);
    atomicAdd(&ssq[f + 2], lq.z);  atomicAdd(&ssq[f + 3], lq.w);
    atomicAdd(&sro[f + 0], lr.x);  atomicAdd(&sro[f + 1], lr.y);
    atomicAdd(&sro[f + 2], lr.z);  atomicAdd(&sro[f + 3], lr.w);
    __syncthreads();
    if (tid < D) {
        atomicAdd(&g_sum[layer][tid], ssum[tid]);
        atomicAdd(&g_sq[layer][tid], ssq[tid]);
        atomicAdd(&g_ro[layer][tid], sro[tid]);
    }
}

// ---------------- normalize + relu: ((tmp + ro) - mean)*scale + beta ----------------
__global__ void __launch_bounds__(256) normalize_kernel(int layer,
                                                        const float* __restrict__ gamma,
                                                        const float* __restrict__ beta) {
    __shared__ float s_sc[D], s_mn[D], s_bt[D], s_ro[D];
    int tid = threadIdx.x;
    if (tid < D) {
        const float inv = 1.0f / (float)N_NODES;
        float mu = g_sum[layer][tid] * inv;
        float var = g_sq[layer][tid] * inv - mu * mu;     // shift-invariant variance
        float ro = g_ro[layer][tid];
        s_sc[tid] = gamma[layer * D + tid] * rsqrtf(var + BN_EPS);
        s_mn[tid] = ro + mu;                              // mean of (a + ro) values
        s_bt[tid] = beta[layer * D + tid];
        s_ro[tid] = ro;
    }
    __syncthreads();
    int fg = tid & 31;
    float4 sc = ((const float4*)s_sc)[fg];
    float4 mn = ((const float4*)s_mn)[fg];
    float4 bt = ((const float4*)s_bt)[fg];
    float4 ro = ((const float4*)s_ro)[fg];
    int t = blockIdx.x * 256 + tid;
    int stride = gridDim.x * 256;
    for (int idx = t; idx < N_NODES * F4; idx += stride) {
        float4 v = g_tmp[idx];
        v.x = fmaxf(fmaf((v.x + ro.x) - mn.x, sc.x, bt.x), 0.f);
        v.y = fmaxf(fmaf((v.y + ro.y) - mn.y, sc.y, bt.y), 0.f);
        v.z = fmaxf(fmaf((v.z + ro.z) - mn.z, sc.z, bt.z), 0.f);
        v.w = fmaxf(fmaf((v.w + ro.w) - mn.w, sc.w, bt.w), 0.f);
        g_h[idx] = v;
    }
}

// ---------------- final: fused (normalize+relu of layer2) @ W + b ----------------
__global__ void __launch_bounds__(256) gemm_kernel(const float* __restrict__ W,
                                                   const float* __restrict__ b,
                                                   const float* __restrict__ gamma,
                                                   const float* __restrict__ beta,
                                                   float4* __restrict__ out) {
    __shared__ float As[128 * 36];  // 128 rows x 32 k (+4 pad)
    __shared__ float Ws[32 * 68];   // 32 k x 64 cols (+4 pad)
    __shared__ float s_sc[D], s_mn[D], s_bt[D], s_ro[D];
    int tid = threadIdx.x;
    if (tid < D) {
        const float inv = 1.0f / (float)N_NODES;
        float mu = g_sum[2][tid] * inv;
        float var = g_sq[2][tid] * inv - mu * mu;
        float ro = g_ro[2][tid];
        s_sc[tid] = gamma[2 * D + tid] * rsqrtf(var + BN_EPS);
        s_mn[tid] = ro + mu;
        s_bt[tid] = beta[2 * D + tid];
        s_ro[tid] = ro;
    }
    __syncthreads();
    int row0 = blockIdx.x * 128;
    int cg = tid & 15;    // column group: cols cg*4 .. cg*4+3
    int rg = tid >> 4;    // row group: rows rg + 16*j
    const float4* W4 = (const float4*)W;
    const float4* sc4 = (const float4*)s_sc;
    const float4* mn4 = (const float4*)s_mn;
    const float4* bt4 = (const float4*)s_bt;
    const float4* ro4 = (const float4*)s_ro;
    float4 acc[8];
#pragma unroll
    for (int j = 0; j < 8; j++) acc[j] = make_float4(0.f, 0.f, 0.f, 0.f);

    for (int kk = 0; kk < 4; kk++) {
#pragma unroll
        for (int it = 0; it < 4; it++) {
            int lin = tid + it * 256;
            int r = lin >> 3;
            int kc = lin & 7;
            int grow = row0 + r;
            float4 a = (grow < N_NODES) ? g_tmp[grow * F4 + kk * 8 + kc]
                                        : make_float4(0.f, 0.f, 0.f, 0.f);
            float4 s = sc4[kk * 8 + kc];
            float4 m = mn4[kk * 8 + kc];
            float4 t = bt4[kk * 8 + kc];
            float4 r4 = ro4[kk * 8 + kc];
            a.x = fmaxf(fmaf((a.x + r4.x) - m.x, s.x, t.x), 0.f);
            a.y = fmaxf(fmaf((a.y + r4.y) - m.y, s.y, t.y), 0.f);
            a.z = fmaxf(fmaf((a.z + r4.z) - m.z, s.z, t.z), 0.f);
            a.w = fmaxf(fmaf((a.w + r4.w) - m.w, s.w, t.w), 0.f);
            *(float4*)&As[r * 36 + kc * 4] = a;
        }
#pragma unroll
        for (int it = 0; it < 2; it++) {
            int lin = tid + it * 256;
            int k = lin >> 4;
            int c4 = lin & 15;
            *(float4*)&Ws[k * 68 + c4 * 4] = W4[(kk * 32 + k) * 16 + c4];
        }
        __syncthreads();
#pragma unroll
        for (int k4 = 0; k4 < 8; k4++) {
            float4 w0 = *(const float4*)&Ws[(k4 * 4 + 0) * 68 + cg * 4];
            float4 w1 = *(const float4*)&Ws[(k4 * 4 + 1) * 68 + cg * 4];
            float4 w2 = *(const float4*)&Ws[(k4 * 4 + 2) * 68 + cg * 4];
            float4 w3 = *(const float4*)&Ws[(k4 * 4 + 3) * 68 + cg * 4];
#pragma unroll
            for (int j = 0; j < 8; j++) {
                float4 a = *(const float4*)&As[(rg + 16 * j) * 36 + k4 * 4];
                acc[j].x = fmaf(a.x, w0.x, fmaf(a.y, w1.x, fmaf(a.z, w2.x, fmaf(a.w, w3.x, acc[j].x))));
                acc[j].y = fmaf(a.x, w0.y, fmaf(a.y, w1.y, fmaf(a.z, w2.y, fmaf(a.w, w3.y, acc[j].y))));
                acc[j].z = fmaf(a.x, w0.z, fmaf(a.y, w1.z, fmaf(a.z, w2.z, fmaf(a.w, w3.z, acc[j].z))));
                acc[j].w = fmaf(a.x, w0.w, fmaf(a.y, w1.w, fmaf(a.z, w2.w, fmaf(a.w, w3.w, acc[j].w))));
            }
        }
        __syncthreads();
    }
    float4 bb = ((const float4*)b)[cg];
#pragma unroll
    for (int j = 0; j < 8; j++) {
        int grow = row0 + rg + 16 * j;
        if (grow < N_NODES) {
            float4 o;
            o.x = acc[j].x + bb.x;
            o.y = acc[j].y + bb.y;
            o.z = acc[j].z + bb.z;
            o.w = acc[j].w + bb.w;
            out[grow * 16 + cg] = o;
        }
    }
}

// ---------------- launch ----------------
extern "C" void kernel_launch(void* const* d_in, const int* in_sizes, int n_in,
                              void* d_out, int out_size) {
    (void)in_sizes; (void)n_in; (void)out_size;
    const float* x = (const float*)d_in[0];
    const int* ei = (const int*)d_in[1];      // int32 per harness dtype table
    const float* gamma = (const float*)d_in[2];
    const float* beta = (const float*)d_in[3];
    const float* W = (const float*)d_in[4];
    const float* b = (const float*)d_in[5];
    float4* out = (float4*)d_out;

    const int WIDE = 1184;  // 8 * 148 SMs
    const int EV4 = (N_EDGES / 4 + 255) / 256;

    zero_kernel<<<(N_NODES + 255) / 256, 256>>>();
    hist_kernel<<<EV4, 256>>>(ei);
    scan_kernel<<<1, 1024>>>();
    fill_kernel<<<EV4, 256>>>(ei);

    for (int layer = 0; layer < 3; layer++) {
        combine_kernel<<<WIDE, 256>>>(layer, (const float4*)x);
        if (layer < 2) normalize_kernel<<<WIDE, 256>>>(layer, gamma, beta);
    }
    gemm_kernel<<<(N_NODES + 127) / 128, 256>>>(W, b, gamma, beta, out);
}